// round 5
// baseline (speedup 1.0000x reference)
#include <cuda_runtime.h>
#include <cuda_bf16.h>
#include <cstdint>

#define NN 50000
#define NE 640000
#define D  128
#define NG 512
#define NBLK ((NN + 255) / 256)
#define MT 64                       /* rows per fused tile */
#define NTILE ((NN + MT - 1) / MT)  /* 782 */

// ---- dynamic smem layout for fused gemm kernels (bytes) ----
#define U_HI_OFF 0                  /* [64][136] bf16 = 17408 */
#define U_LO_OFF 17408
#define V_OFF    34816              /* [2 buf][2 hl][64][40] bf16, 5120 each */
#define B_OFF    55296              /* [2 buf][2 hl][32][136] bf16, 8704 each */
#define SB_OFF   90112              /* float[128] */
#define FUSED_SMEM 90624

// ---------------- scratch (static device globals) --------------------------
__device__ __align__(16) float g_h0[NN * D];
__device__ __align__(16) float g_h1[NN * D];
__device__ __align__(16) __nv_bfloat16 g_vhi[NN * D];
__device__ __align__(16) __nv_bfloat16 g_vlo[NN * D];
__device__ __align__(16) __nv_bfloat16 g_Whi[4 * 256 * 128];
__device__ __align__(16) __nv_bfloat16 g_Wlo[4 * 256 * 128];
__device__ __align__(16) float g_Wcomb[256 * 128];
__device__ __align__(16) float g_pooled[NG * D];
__device__ float g_bw[128];
__device__ float g_t0[128];
__device__ float g_invdeg[NN];
__device__ float g_c[NN];
__device__ int   g_indeg[NN];
__device__ int   g_rowptr[NN + 1];
__device__ int   g_fill[NN];
__device__ int   g_bsum[NBLK + 32];
__device__ int   g_csr_src[NE];
__device__ int   g_csr_eid[NE];

// ---------------- helpers ---------------------------------------------------
__device__ __forceinline__ unsigned short bf_bits(__nv_bfloat16 h) {
    unsigned short u; memcpy(&u, &h, 2); return u;
}
__device__ __forceinline__ void split4(float4 a, uint2& hi, uint2& lo) {
    __nv_bfloat16 h0 = __float2bfloat16(a.x), h1 = __float2bfloat16(a.y);
    __nv_bfloat16 h2 = __float2bfloat16(a.z), h3 = __float2bfloat16(a.w);
    __nv_bfloat16 l0 = __float2bfloat16(a.x - __bfloat162float(h0));
    __nv_bfloat16 l1 = __float2bfloat16(a.y - __bfloat162float(h1));
    __nv_bfloat16 l2 = __float2bfloat16(a.z - __bfloat162float(h2));
    __nv_bfloat16 l3 = __float2bfloat16(a.w - __bfloat162float(h3));
    hi.x = (unsigned)bf_bits(h0) | ((unsigned)bf_bits(h1) << 16);
    hi.y = (unsigned)bf_bits(h2) | ((unsigned)bf_bits(h3) << 16);
    lo.x = (unsigned)bf_bits(l0) | ((unsigned)bf_bits(l1) << 16);
    lo.y = (unsigned)bf_bits(l2) | ((unsigned)bf_bits(l3) << 16);
}
__device__ __forceinline__ uint32_t sptr(const void* p) {
    return (uint32_t)__cvta_generic_to_shared(p);
}

#define LDSM4(R, addr) \
    asm volatile("ldmatrix.sync.aligned.m8n8.x4.shared.b16 {%0,%1,%2,%3},[%4];" \
        : "=r"((R)[0]), "=r"((R)[1]), "=r"((R)[2]), "=r"((R)[3]) : "r"(addr))
#define LDSM4T(R, addr) \
    asm volatile("ldmatrix.sync.aligned.m8n8.x4.trans.shared.b16 {%0,%1,%2,%3},[%4];" \
        : "=r"((R)[0]), "=r"((R)[1]), "=r"((R)[2]), "=r"((R)[3]) : "r"(addr))
#define MMA(C, A, B) \
    asm volatile("mma.sync.aligned.m16n8k16.row.col.f32.bf16.bf16.f32 " \
        "{%0,%1,%2,%3},{%4,%5,%6,%7},{%8,%9},{%0,%1,%2,%3};" \
        : "+f"((C)[0]), "+f"((C)[1]), "+f"((C)[2]), "+f"((C)[3]) \
        : "r"((A)[0]), "r"((A)[1]), "r"((A)[2]), "r"((A)[3]), "r"((B)[0]), "r"((B)[1]))
#define CP16(dst, src) \
    asm volatile("cp.async.cg.shared.global [%0], [%1], 16;" :: "r"(dst), "l"(src))
#define CPCOMMIT() asm volatile("cp.async.commit_group;")
#define CPWAIT(n)  asm volatile("cp.async.wait_group %0;" :: "n"(n))

// ---------------- init / CSR build -----------------------------------------
__global__ void k_zero() {
    int i = blockIdx.x * blockDim.x + threadIdx.x;
    if (i < NN) { g_indeg[i] = 0; g_fill[i] = 0; }
    if (i < NG * D) g_pooled[i] = 0.f;
}
__global__ void k_count(const int* __restrict__ ei) {
    int e = blockIdx.x * blockDim.x + threadIdx.x;
    if (e < NE) atomicAdd(&g_indeg[ei[NE + e]], 1);
}
__global__ void k_scan1() {
    __shared__ int sm[8];
    int t = threadIdx.x, lane = t & 31, wid = t >> 5;
    int i = blockIdx.x * 256 + t;
    int v = (i < NN) ? g_indeg[i] : 0;
#pragma unroll
    for (int s = 16; s > 0; s >>= 1) v += __shfl_down_sync(0xffffffffu, v, s);
    if (lane == 0) sm[wid] = v;
    __syncthreads();
    if (t == 0) {
        int s = 0;
#pragma unroll
        for (int w = 0; w < 8; w++) s += sm[w];
        g_bsum[blockIdx.x] = s;
    }
}
__global__ void k_scan2() {
    __shared__ int ws[8];
    int t = threadIdx.x, lane = t & 31, wid = t >> 5;
    int v = (t < NBLK) ? g_bsum[t] : 0;
    int x = v;
#pragma unroll
    for (int s = 1; s < 32; s <<= 1) {
        int tt = __shfl_up_sync(0xffffffffu, x, s);
        if (lane >= s) x += tt;
    }
    if (lane == 31) ws[wid] = x;
    __syncthreads();
    if (t == 0) {
        int acc = 0;
#pragma unroll
        for (int w = 0; w < 8; w++) { int tmp = ws[w]; ws[w] = acc; acc += tmp; }
    }
    __syncthreads();
    int excl = ws[wid] + x - v;
    if (t < NBLK) g_bsum[t] = excl;
    if (t == NBLK - 1) g_rowptr[NN] = excl + v;
}
__global__ void k_scan3() {
    __shared__ int ws[8];
    int t = threadIdx.x, lane = t & 31, wid = t >> 5;
    int i = blockIdx.x * 256 + t;
    int v = (i < NN) ? g_indeg[i] : 0;
    int x = v;
#pragma unroll
    for (int s = 1; s < 32; s <<= 1) {
        int tt = __shfl_up_sync(0xffffffffu, x, s);
        if (lane >= s) x += tt;
    }
    if (lane == 31) ws[wid] = x;
    __syncthreads();
    if (t == 0) {
        int acc = 0;
#pragma unroll
        for (int w = 0; w < 8; w++) { int tmp = ws[w]; ws[w] = acc; acc += tmp; }
    }
    __syncthreads();
    if (i < NN) {
        g_rowptr[i] = g_bsum[blockIdx.x] + ws[wid] + x - v;
        g_invdeg[i] = 1.0f / fmaxf((float)v, 1.0f);
        g_c[i] = (v > 0) ? 2.0f : 1.0f;
    }
}
__global__ void k_fill(const int* __restrict__ ei) {
    int e = blockIdx.x * blockDim.x + threadIdx.x;
    if (e < NE) {
        int dst = ei[NE + e];
        int p = g_rowptr[dst] + atomicAdd(&g_fill[dst], 1);
        g_csr_src[p] = ei[e];
        g_csr_eid[p] = e;
    }
}

// pre-split stacked weights [W_l ; We_l] (layers 0..3), flat k-major
__global__ void k_wsplit(const float* __restrict__ Ws, const float* __restrict__ Wes) {
    int i = blockIdx.x * blockDim.x + threadIdx.x;
    if (i >= 4 * 256 * 128) return;
    int l = i >> 15, rem = i & 32767;
    int k = rem >> 7, n = rem & 127;
    float v = (k < 128) ? Ws[l * 16384 + k * 128 + n]
                        : Wes[l * 16384 + (k - 128) * 128 + n];
    __nv_bfloat16 h = __float2bfloat16(v);
    __nv_bfloat16 lo = __float2bfloat16(v - __bfloat162float(h));
    g_Whi[i] = h;
    g_Wlo[i] = lo;
}

// r0 + b0 (rank-1 layer-0 shortcut)
__global__ void k_r0(const float* __restrict__ emb, const float* __restrict__ bs,
                     const float* __restrict__ Ws) {
    int t = threadIdx.x;
    float acc = bs[t];
#pragma unroll 8
    for (int k = 0; k < 128; k++) acc = fmaf(emb[k], Ws[k * 128 + t], acc);
    g_t0[t] = acc;
}

// Wcomb = [W4;We4] @ Wp, bw = b4 @ Wp
__global__ void k_comb(const float* __restrict__ Ws, const float* __restrict__ Wes,
                       const float* __restrict__ bs, const float* __restrict__ Wp) {
    if (blockIdx.x == 128) {
        int t = threadIdx.x;
        if (t < 128) {
            float acc = 0.f;
#pragma unroll 8
            for (int k = 0; k < 128; k++) acc = fmaf(bs[4 * 128 + k], Wp[k * 128 + t], acc);
            g_bw[t] = acc;
        }
        return;
    }
    int i = blockIdx.x * 256 + threadIdx.x;
    int r = i >> 7, c = i & 127;
    const float* Wrow = (r < 128) ? (Ws + 4 * 16384 + r * 128)
                                  : (Wes + 4 * 16384 + (r - 128) * 128);
    float acc = 0.f;
#pragma unroll 8
    for (int k = 0; k < 128; k++) acc = fmaf(Wrow[k], Wp[k * 128 + c], acc);
    g_Wcomb[i] = acc;
}

// =============== shared GEMM micro-kernel pieces (8 warps, 64x128 tile) =====
struct FusedSmem {
    __nv_bfloat16* u_hi;   // [64][136]
    __nv_bfloat16* u_lo;
    char* base;
    float* sb;
    __device__ void init(char* dyn) {
        base = dyn;
        u_hi = (__nv_bfloat16*)(dyn + U_HI_OFF);
        u_lo = (__nv_bfloat16*)(dyn + U_LO_OFF);
        sb = (float*)(dyn + SB_OFF);
    }
    __device__ uint32_t vbuf(int buf, int hl) const {
        return sptr(base + V_OFF) + (buf * 2 + hl) * 5120;
    }
    __device__ uint32_t bbuf(int buf, int hl) const {
        return sptr(base + B_OFF) + (buf * 2 + hl) * 8704;
    }
};

// ================= fused layer-0: k_v gather + GEMM(v @ We0) ================
__global__ __launch_bounds__(256) void k_fused_l0(const float* __restrict__ ea) {
    extern __shared__ char dyn[];
    FusedSmem S; S.init(dyn);
    int tid = threadIdx.x, warp = tid >> 5, l = tid & 31;
    int row0 = blockIdx.x * MT;

    const __nv_bfloat16* Whi = g_Whi;     // layer 0
    const __nv_bfloat16* Wlo = g_Wlo;
    int bk = tid >> 3, bsc = (tid & 7) * 2;

    auto issueB = [&](int s, int buf) {
        const __nv_bfloat16* bh = Whi + (s * 32 + bk) * 128 + bsc * 8;
        const __nv_bfloat16* bl = Wlo + (s * 32 + bk) * 128 + bsc * 8;
        uint32_t eh = S.bbuf(buf, 0) + (bk * 136 + bsc * 8) * 2;
        uint32_t el = S.bbuf(buf, 1) + (bk * 136 + bsc * 8) * 2;
        CP16(eh, bh); CP16(eh + 16, bh + 8);
        CP16(el, bl); CP16(el + 16, bl + 8);
        CPCOMMIT();
    };

    if (tid < 128) S.sb[tid] = g_t0[tid];
    issueB(4, 0);   // first B stage overlaps the gather

    // ---- phase 1: gather edge_attr, v = EA/deg, write smem(resident)+global
    {
        const float4* ea4 = (const float4*)ea;
#pragma unroll 1
        for (int j = 0; j < 8; j++) {
            int rr = warp * 8 + j;
            int w = row0 + rr;
            float4 acc = make_float4(0.f, 0.f, 0.f, 0.f);
            if (w < NN) {
                int s = g_rowptr[w], t = g_rowptr[w + 1];
                int p = s;
                for (; p + 1 < t; p += 2) {
                    int e0 = g_csr_eid[p], e1 = g_csr_eid[p + 1];
                    float4 x0 = ea4[e0 * 32 + l];
                    float4 x1 = ea4[e1 * 32 + l];
                    acc.x += x0.x + x1.x; acc.y += x0.y + x1.y;
                    acc.z += x0.z + x1.z; acc.w += x0.w + x1.w;
                }
                if (p < t) {
                    float4 x0 = ea4[g_csr_eid[p] * 32 + l];
                    acc.x += x0.x; acc.y += x0.y; acc.z += x0.z; acc.w += x0.w;
                }
                float id = g_invdeg[w];
                acc.x *= id; acc.y *= id; acc.z *= id; acc.w *= id;
            }
            uint2 hi, lo; split4(acc, hi, lo);
            *(uint2*)&S.u_hi[rr * 136 + l * 4] = hi;
            *(uint2*)&S.u_lo[rr * 136 + l * 4] = lo;
            if (w < NN) {
                ((uint2*)g_vhi)[w * 32 + l] = hi;
                ((uint2*)g_vlo)[w * 32 + l] = lo;
            }
        }
    }
    __syncthreads();

    // ---- phase 2: GEMM, K=128 (B chunks 4..7 of layer0 stack, A resident)
    float acc[8][4];
#pragma unroll
    for (int b = 0; b < 8; b++)
#pragma unroll
        for (int c = 0; c < 4; c++) acc[b][c] = 0.f;

    int wm = (warp >> 1) * 16, wn = (warp & 1) * 64;
    int rA = l & 15, cA = (l >> 4) * 8;
    uint32_t aHiR = sptr(S.u_hi) + ((wm + rA) * 136 + cA) * 2;
    uint32_t aLoR = sptr(S.u_lo) + ((wm + rA) * 136 + cA) * 2;

#pragma unroll 1
    for (int s = 4; s < 8; s++) {
        int buf = (s - 4) & 1;
        if (s + 1 < 8) issueB(s + 1, buf ^ 1);
        if (s + 1 < 8) { CPWAIT(1); } else { CPWAIT(0); }
        __syncthreads();
        uint32_t bHi = S.bbuf(buf, 0) + (rA * 136 + wn + cA) * 2;
        uint32_t bLo = S.bbuf(buf, 1) + (rA * 136 + wn + cA) * 2;
        int ares = (s - 4) * 32;
#pragma unroll
        for (int ks = 0; ks < 2; ks++) {
            int k16 = ks * 16;
            uint32_t ah[4], al[4];
            LDSM4(ah, aHiR + (ares + k16) * 2);
            LDSM4(al, aLoR + (ares + k16) * 2);
#pragma unroll
            for (int ng = 0; ng < 4; ng++) {
                uint32_t bh[4], bl[4];
                LDSM4T(bh, bHi + (k16 * 136 + ng * 16) * 2);
                LDSM4T(bl, bLo + (k16 * 136 + ng * 16) * 2);
#pragma unroll
                for (int sub = 0; sub < 2; sub++) {
                    float* C = acc[ng * 2 + sub];
                    MMA(C, ah, &bh[sub * 2]);
                    MMA(C, ah, &bl[sub * 2]);
                    MMA(C, al, &bh[sub * 2]);
                }
            }
        }
        __syncthreads();
    }

    // epilogue: h0 = relu(acc + c * t0)
    int gq = l >> 2, tg = l & 3;
    int r1 = row0 + wm + gq, r2 = r1 + 8;
    float c1 = (r1 < NN) ? g_c[r1] : 0.f;
    float c2 = (r2 < NN) ? g_c[r2] : 0.f;
#pragma unroll
    for (int nt = 0; nt < 8; nt++) {
        int col = wn + nt * 8 + tg * 2;
        float b0 = S.sb[col], b1 = S.sb[col + 1];
        float* C = acc[nt];
        float v0 = fmaxf(C[0] + c1 * b0, 0.f), v1 = fmaxf(C[1] + c1 * b1, 0.f);
        float v2 = fmaxf(C[2] + c2 * b0, 0.f), v3 = fmaxf(C[3] + c2 * b1, 0.f);
        if (r1 < NN) *(float2*)&g_h0[r1 * 128 + col] = make_float2(v0, v1);
        if (r2 < NN) *(float2*)&g_h0[r2 * 128 + col] = make_float2(v2, v3);
    }
}

// ====== fused mid layer: spmm gather + GEMM([u|v] @ [W;We]) , l = 1..3 ======
__global__ __launch_bounds__(256) void k_fused_mid(
    int layer, const float* __restrict__ hin, float* __restrict__ hout,
    const float* __restrict__ tvec) {
    extern __shared__ char dyn[];
    FusedSmem S; S.init(dyn);
    int tid = threadIdx.x, warp = tid >> 5, l = tid & 31;
    int row0 = blockIdx.x * MT;

    const __nv_bfloat16* Whi = g_Whi + layer * 32768;
    const __nv_bfloat16* Wlo = g_Wlo + layer * 32768;
    int bk = tid >> 3, bsc = (tid & 7) * 2;
    int vr = tid >> 2, vc = tid & 3;

    auto issueStage = [&](int s, int buf) {
        const __nv_bfloat16* bh = Whi + (s * 32 + bk) * 128 + bsc * 8;
        const __nv_bfloat16* bl = Wlo + (s * 32 + bk) * 128 + bsc * 8;
        uint32_t eh = S.bbuf(buf, 0) + (bk * 136 + bsc * 8) * 2;
        uint32_t el = S.bbuf(buf, 1) + (bk * 136 + bsc * 8) * 2;
        CP16(eh, bh); CP16(eh + 16, bh + 8);
        CP16(el, bl); CP16(el + 16, bl + 8);
        if (s >= 4) {
            int grow = row0 + vr; if (grow >= NN) grow = NN - 1;
            const __nv_bfloat16* vh = g_vhi + grow * 128 + (s - 4) * 32 + vc * 8;
            const __nv_bfloat16* vl = g_vlo + grow * 128 + (s - 4) * 32 + vc * 8;
            CP16(S.vbuf(buf, 0) + (vr * 40 + vc * 8) * 2, vh);
            CP16(S.vbuf(buf, 1) + (vr * 40 + vc * 8) * 2, vl);
        }
        CPCOMMIT();
    };

    if (tid < 128) S.sb[tid] = tvec[tid];
    issueStage(0, 0);

    // ---- phase 1: u = h + (sum h[src])/deg -> split to resident smem
    {
        const float4* h4 = (const float4*)hin;
#pragma unroll 1
        for (int j = 0; j < 8; j++) {
            int rr = warp * 8 + j;
            int w = row0 + rr;
            float4 acc = make_float4(0.f, 0.f, 0.f, 0.f);
            if (w < NN) {
                int s = g_rowptr[w], t = g_rowptr[w + 1];
                int p = s;
                for (; p + 1 < t; p += 2) {
                    int s0 = g_csr_src[p], s1 = g_csr_src[p + 1];
                    float4 x0 = h4[s0 * 32 + l];
                    float4 x1 = h4[s1 * 32 + l];
                    acc.x += x0.x + x1.x; acc.y += x0.y + x1.y;
                    acc.z += x0.z + x1.z; acc.w += x0.w + x1.w;
                }
                if (p < t) {
                    float4 x0 = h4[g_csr_src[p] * 32 + l];
                    acc.x += x0.x; acc.y += x0.y; acc.z += x0.z; acc.w += x0.w;
                }
                float id = g_invdeg[w];
                float4 hh = h4[w * 32 + l];
                acc.x = hh.x + acc.x * id; acc.y = hh.y + acc.y * id;
                acc.z = hh.z + acc.z * id; acc.w = hh.w + acc.w * id;
            }
            uint2 hi, lo; split4(acc, hi, lo);
            *(uint2*)&S.u_hi[rr * 136 + l * 4] = hi;
            *(uint2*)&S.u_lo[rr * 136 + l * 4] = lo;
        }
    }
    __syncthreads();

    // ---- phase 2: GEMM K=256: chunks 0-3 resident u, 4-7 cp.async v
    float acc[8][4];
#pragma unroll
    for (int b = 0; b < 8; b++)
#pragma unroll
        for (int c = 0; c < 4; c++) acc[b][c] = 0.f;

    int wm = (warp >> 1) * 16, wn = (warp & 1) * 64;
    int rA = l & 15, cA = (l >> 4) * 8;
    uint32_t aHiR = sptr(S.u_hi) + ((wm + rA) * 136 + cA) * 2;
    uint32_t aLoR = sptr(S.u_lo) + ((wm + rA) * 136 + cA) * 2;

#pragma unroll 1
    for (int s = 0; s < 8; s++) {
        int buf = s & 1;
        if (s + 1 < 8) issueStage(s + 1, buf ^ 1);
        if (s + 1 < 8) { CPWAIT(1); } else { CPWAIT(0); }
        __syncthreads();
        uint32_t bHi = S.bbuf(buf, 0) + (rA * 136 + wn + cA) * 2;
        uint32_t bLo = S.bbuf(buf, 1) + (rA * 136 + wn + cA) * 2;
        bool res = (s < 4);
        uint32_t aH = res ? (aHiR + s * 64) /* s*32 elems *2B */ 
                          : (S.vbuf(buf, 0) + ((wm + rA) * 40 + cA) * 2);
        uint32_t aL = res ? (aLoR + s * 64)
                          : (S.vbuf(buf, 1) + ((wm + rA) * 40 + cA) * 2);
        int astride = res ? 136 : 40;  // unused below; k16 offset explicit
#pragma unroll
        for (int ks = 0; ks < 2; ks++) {
            int k16 = ks * 16;
            uint32_t ah[4], al[4];
            LDSM4(ah, aH + k16 * 2);
            LDSM4(al, aL + k16 * 2);
#pragma unroll
            for (int ng = 0; ng < 4; ng++) {
                uint32_t bh[4], bl[4];
                LDSM4T(bh, bHi + (k16 * 136 + ng * 16) * 2);
                LDSM4T(bl, bLo + (k16 * 136 + ng * 16) * 2);
#pragma unroll
                for (int sub = 0; sub < 2; sub++) {
                    float* C = acc[ng * 2 + sub];
                    MMA(C, ah, &bh[sub * 2]);
                    MMA(C, ah, &bl[sub * 2]);
                    MMA(C, al, &bh[sub * 2]);
                }
            }
        }
        (void)astride;
        __syncthreads();
    }

    // epilogue
    int gq = l >> 2, tg = l & 3;
    int r1 = row0 + wm + gq, r2 = r1 + 8;
    float c1 = (r1 < NN) ? g_c[r1] : 0.f;
    float c2 = (r2 < NN) ? g_c[r2] : 0.f;
#pragma unroll
    for (int nt = 0; nt < 8; nt++) {
        int col = wn + nt * 8 + tg * 2;
        float b0 = S.sb[col], b1 = S.sb[col + 1];
        float* C = acc[nt];
        float v0 = fmaxf(C[0] + c1 * b0, 0.f), v1 = fmaxf(C[1] + c1 * b1, 0.f);
        float v2 = fmaxf(C[2] + c2 * b0, 0.f), v3 = fmaxf(C[3] + c2 * b1, 0.f);
        if (r1 < NN) *(float2*)&hout[r1 * 128 + col] = make_float2(v0, v1);
        if (r2 < NN) *(float2*)&hout[r2 * 128 + col] = make_float2(v2, v3);
    }
}

// ==== fused final: spmm_f32 gather + per-graph column sums (batch sorted) ===
__global__ __launch_bounds__(256) void k_fused_last(
    const float* __restrict__ hin, const int* __restrict__ batch) {
    __shared__ float uf[MT][132];
    __shared__ int sbatch[MT];
    int tid = threadIdx.x, warp = tid >> 5, l = tid & 31;
    int row0 = blockIdx.x * MT;
    int nvalid = NN - row0; if (nvalid > MT) nvalid = MT;

    if (tid < MT && tid < nvalid) sbatch[tid] = batch[row0 + tid];

    const float4* h4 = (const float4*)hin;
#pragma unroll 1
    for (int j = 0; j < 8; j++) {
        int rr = warp * 8 + j;
        int w = row0 + rr;
        float4 acc = make_float4(0.f, 0.f, 0.f, 0.f);
        if (w < NN) {
            int s = g_rowptr[w], t = g_rowptr[w + 1];
            int p = s;
            for (; p + 1 < t; p += 2) {
                int s0 = g_csr_src[p], s1 = g_csr_src[p + 1];
                float4 x0 = h4[s0 * 32 + l];
                float4 x1 = h4[s1 * 32 + l];
                acc.x += x0.x + x1.x; acc.y += x0.y + x1.y;
                acc.z += x0.z + x1.z; acc.w += x0.w + x1.w;
            }
            if (p < t) {
                float4 x0 = h4[g_csr_src[p] * 32 + l];
                acc.x += x0.x; acc.y += x0.y; acc.z += x0.z; acc.w += x0.w;
            }
            float id = g_invdeg[w];
            float4 hh = h4[w * 32 + l];
            acc.x = hh.x + acc.x * id; acc.y = hh.y + acc.y * id;
            acc.z = hh.z + acc.z * id; acc.w = hh.w + acc.w * id;
        }
        *(float4*)&uf[rr][l * 4] = acc;
    }
    __syncthreads();

    if (tid < 128 && nvalid > 0) {
        float acc = 0.f;
        int cur = sbatch[0];
        for (int r = 0; r < nvalid; r++) {
            int b = sbatch[r];
            if (b != cur) {
                atomicAdd(&g_pooled[cur * 128 + tid], acc);
                acc = 0.f; cur = b;
            }
            acc += uf[r][tid];
        }
        atomicAdd(&g_pooled[cur * 128 + tid], acc);
    }
}

// ---------------- pooled classifier -----------------------------------------
__device__ __forceinline__ int lower_bound(const int* a, int n, int key) {
    int lo = 0, hi = n;
    while (lo < hi) {
        int mid = (lo + hi) >> 1;
        if (a[mid] < key) lo = mid + 1; else hi = mid;
    }
    return lo;
}

__global__ void k_pool_out(const int* __restrict__ batch,
                           const float* __restrict__ bp,
                           float* __restrict__ out) {
    int g = blockIdx.x, t = threadIdx.x;
    __shared__ int s_lo, s_hi;
    __shared__ float sp[256];
    __shared__ float spc[256];
    if (t == 0) s_lo = lower_bound(batch, NN, g);
    if (t == 1) s_hi = lower_bound(batch, NN, g + 1);
    __syncthreads();
    int lo = s_lo, hi = s_hi;
    float inv = 1.f / fmaxf((float)(hi - lo), 1.f);
    float sum = 0.f;
    if (t < 128) {
        sum = g_pooled[g * 128 + t];          // precomputed u-sum
    } else {
        int q = t - 128;
        for (int r = lo; r < hi; r++)
            sum += __bfloat162float(g_vhi[r * 128 + q]) + __bfloat162float(g_vlo[r * 128 + q]);
    }
    float csum = 0.f;
    for (int r = lo + t; r < hi; r += 256) csum += g_c[r];
    sp[t] = sum * inv;
    spc[t] = csum;
    __syncthreads();
#pragma unroll
    for (int s = 128; s > 0; s >>= 1) {
        if (t < s) spc[t] += spc[t + s];
        __syncthreads();
    }
    float pcm = spc[0] * inv;
    if (t < 128) {
        float acc = fmaf(pcm, g_bw[t], bp[t]);
#pragma unroll 8
        for (int k = 0; k < 256; k++) acc = fmaf(sp[k], g_Wcomb[k * 128 + t], acc);
        out[g * 128 + t] = acc;
    }
}

// ---------------- launch ----------------------------------------------------
extern "C" void kernel_launch(void* const* d_in, const int* in_sizes, int n_in,
                              void* d_out, int out_size) {
    const int*   ei    = (const int*)d_in[1];
    const float* ea    = (const float*)d_in[2];
    const int*   batch = (const int*)d_in[3];
    const float* emb   = (const float*)d_in[4];
    const float* Ws    = (const float*)d_in[5];
    const float* bs    = (const float*)d_in[6];
    const float* Wes   = (const float*)d_in[7];
    const float* Wp    = (const float*)d_in[8];
    const float* bp    = (const float*)d_in[9];
    float* out = (float*)d_out;

    static bool attr_done = false;
    if (!attr_done) {
        cudaFuncSetAttribute(k_fused_l0, cudaFuncAttributeMaxDynamicSharedMemorySize,
                             FUSED_SMEM);
        cudaFuncSetAttribute(k_fused_mid, cudaFuncAttributeMaxDynamicSharedMemorySize,
                             FUSED_SMEM);
        attr_done = true;
    }

    float* h0; float* h1;
    cudaGetSymbolAddress((void**)&h0, g_h0);
    cudaGetSymbolAddress((void**)&h1, g_h1);

    k_zero<<<256, 256>>>();
    k_count<<<(NE + 255) / 256, 256>>>(ei);
    k_scan1<<<NBLK, 256>>>();
    k_scan2<<<1, 256>>>();
    k_scan3<<<NBLK, 256>>>();
    k_fill<<<(NE + 255) / 256, 256>>>(ei);
    k_wsplit<<<(4 * 256 * 128 + 255) / 256, 256>>>(Ws, Wes);
    k_r0<<<1, 128>>>(emb, bs, Ws);
    k_comb<<<129, 256>>>(Ws, Wes, bs, Wp);

    // layer 0: fused edge-gather + GEMM(v @ We0) -> h0
    k_fused_l0<<<NTILE, 256, FUSED_SMEM>>>(ea);
    // layers 1..3: fused spmm + GEMM, ping-pong h buffers
    k_fused_mid<<<NTILE, 256, FUSED_SMEM>>>(1, h0, h1, bs + 1 * 128);
    k_fused_mid<<<NTILE, 256, FUSED_SMEM>>>(2, h1, h0, bs + 2 * 128);
    k_fused_mid<<<NTILE, 256, FUSED_SMEM>>>(3, h0, h1, bs + 3 * 128);
    // layer 4 collapsed: fused spmm + per-graph pooling
    k_fused_last<<<NTILE, 256>>>(h1, batch);
    k_pool_out<<<NG, 256>>>(batch, bp, out);
}

// round 6
// speedup vs baseline: 1.1491x; 1.1491x over previous
#include <cuda_runtime.h>
#include <cuda_bf16.h>
#include <cstdint>

#define NN 50000
#define NE 640000
#define D  128
#define NG 512
#define NBLK ((NN + 255) / 256)

// row split for two-stream pipelining
#define ROWS_A 25088              /* 196 tiles * 128 */
#define ROWS_B (NN - ROWS_A)      /* 24912 */
#define TILE_A 196
#define TILE_B 195
#define GR_A_SPMM (ROWS_A / 8)    /* 3136 blocks of 256 thr (8 warps=8 rows) */
#define GR_B_SPMM (ROWS_B / 8)    /* 3114 */

// dynamic smem layout for k_gemm (bytes)
#define A_HI_OFF 0        // [2][128][40] bf16 : 2*10240
#define A_LO_OFF 20480
#define B_HI_OFF 40960    // [2][32][136] bf16 : 2*8704
#define B_LO_OFF 58368
#define SB_OFF   75776    // float[128]
#define GEMM_SMEM 76288
#define ABUF 10240
#define BBUF 8704

// ---------------- scratch (static device globals) --------------------------
__device__ __align__(16) float g_ha[NN * D];
__device__ __align__(16) float g_hb[NN * D];
__device__ __align__(16) float g_u32[NN * D];
__device__ __align__(16) __nv_bfloat16 g_uhi[NN * D];
__device__ __align__(16) __nv_bfloat16 g_ulo[NN * D];
__device__ __align__(16) __nv_bfloat16 g_vhi[NN * D];
__device__ __align__(16) __nv_bfloat16 g_vlo[NN * D];
__device__ __align__(16) __nv_bfloat16 g_Whi[4 * 256 * 128];
__device__ __align__(16) __nv_bfloat16 g_Wlo[4 * 256 * 128];
__device__ __align__(16) float g_Wcomb[256 * 128];
__device__ float g_bw[128];
__device__ float g_t0[128];
__device__ float g_invdeg[NN];
__device__ float g_c[NN];
__device__ int   g_indeg[NN];
__device__ int   g_rowptr[NN + 1];
__device__ int   g_fill[NN];
__device__ int   g_bsum[NBLK + 32];
__device__ __align__(8) int2 g_csr[NE];     // (src, eid)

// ---------------- helpers ---------------------------------------------------
__device__ __forceinline__ unsigned short bf_bits(__nv_bfloat16 h) {
    unsigned short u; memcpy(&u, &h, 2); return u;
}
__device__ __forceinline__ void split4(float4 a, uint2& hi, uint2& lo) {
    __nv_bfloat16 h0 = __float2bfloat16(a.x), h1 = __float2bfloat16(a.y);
    __nv_bfloat16 h2 = __float2bfloat16(a.z), h3 = __float2bfloat16(a.w);
    __nv_bfloat16 l0 = __float2bfloat16(a.x - __bfloat162float(h0));
    __nv_bfloat16 l1 = __float2bfloat16(a.y - __bfloat162float(h1));
    __nv_bfloat16 l2 = __float2bfloat16(a.z - __bfloat162float(h2));
    __nv_bfloat16 l3 = __float2bfloat16(a.w - __bfloat162float(h3));
    hi.x = (unsigned)bf_bits(h0) | ((unsigned)bf_bits(h1) << 16);
    hi.y = (unsigned)bf_bits(h2) | ((unsigned)bf_bits(h3) << 16);
    lo.x = (unsigned)bf_bits(l0) | ((unsigned)bf_bits(l1) << 16);
    lo.y = (unsigned)bf_bits(l2) | ((unsigned)bf_bits(l3) << 16);
}
__device__ __forceinline__ uint32_t sptr(const void* p) {
    return (uint32_t)__cvta_generic_to_shared(p);
}

#define LDSM4(R, addr) \
    asm volatile("ldmatrix.sync.aligned.m8n8.x4.shared.b16 {%0,%1,%2,%3},[%4];" \
        : "=r"((R)[0]), "=r"((R)[1]), "=r"((R)[2]), "=r"((R)[3]) : "r"(addr))
#define LDSM4T(R, addr) \
    asm volatile("ldmatrix.sync.aligned.m8n8.x4.trans.shared.b16 {%0,%1,%2,%3},[%4];" \
        : "=r"((R)[0]), "=r"((R)[1]), "=r"((R)[2]), "=r"((R)[3]) : "r"(addr))
#define MMA(C, A, B) \
    asm volatile("mma.sync.aligned.m16n8k16.row.col.f32.bf16.bf16.f32 " \
        "{%0,%1,%2,%3},{%4,%5,%6,%7},{%8,%9},{%0,%1,%2,%3};" \
        : "+f"((C)[0]), "+f"((C)[1]), "+f"((C)[2]), "+f"((C)[3]) \
        : "r"((A)[0]), "r"((A)[1]), "r"((A)[2]), "r"((A)[3]), "r"((B)[0]), "r"((B)[1]))
#define CP16(dst, src) \
    asm volatile("cp.async.cg.shared.global [%0], [%1], 16;" :: "r"(dst), "l"(src))
#define CPCOMMIT() asm volatile("cp.async.commit_group;")
#define CPWAIT(n)  asm volatile("cp.async.wait_group %0;" :: "n"(n))

// ---------------- init / CSR build -----------------------------------------
__global__ void k_zero() {
    int i = blockIdx.x * blockDim.x + threadIdx.x;
    if (i < NN) g_indeg[i] = 0;
}
__global__ void k_count(const int* __restrict__ ei) {
    int e = blockIdx.x * blockDim.x + threadIdx.x;
    if (e < NE) atomicAdd(&g_indeg[ei[NE + e]], 1);
}
__global__ void k_scan1() {
    __shared__ int sm[8];
    int t = threadIdx.x, lane = t & 31, wid = t >> 5;
    int i = blockIdx.x * 256 + t;
    int v = (i < NN) ? g_indeg[i] : 0;
#pragma unroll
    for (int s = 16; s > 0; s >>= 1) v += __shfl_down_sync(0xffffffffu, v, s);
    if (lane == 0) sm[wid] = v;
    __syncthreads();
    if (t == 0) {
        int s = 0;
#pragma unroll
        for (int w = 0; w < 8; w++) s += sm[w];
        g_bsum[blockIdx.x] = s;
    }
}
// block-local scan + in-kernel offset reduction (replaces scan2+scan3), zeroes fill
__global__ void k_scan3z() {
    __shared__ int red[8];
    __shared__ int ws[8];
    __shared__ int s_base, s_tot;
    int t = threadIdx.x, lane = t & 31, wid = t >> 5;
    int part = 0;
    for (int j = t; j < blockIdx.x; j += 256) part += g_bsum[j];
#pragma unroll
    for (int s = 16; s > 0; s >>= 1) part += __shfl_down_sync(0xffffffffu, part, s);
    if (lane == 0) red[wid] = part;
    __syncthreads();
    if (t == 0) {
        int b = 0;
#pragma unroll
        for (int w = 0; w < 8; w++) b += red[w];
        s_base = b;
    }
    int i = blockIdx.x * 256 + t;
    int v = (i < NN) ? g_indeg[i] : 0;
    int x = v;
#pragma unroll
    for (int s = 1; s < 32; s <<= 1) {
        int tt = __shfl_up_sync(0xffffffffu, x, s);
        if (lane >= s) x += tt;
    }
    if (lane == 31) ws[wid] = x;
    __syncthreads();
    if (t == 0) {
        int acc = 0;
#pragma unroll
        for (int w = 0; w < 8; w++) { int tmp = ws[w]; ws[w] = acc; acc += tmp; }
        s_tot = acc;
    }
    __syncthreads();
    if (i < NN) {
        g_rowptr[i] = s_base + ws[wid] + x - v;
        g_invdeg[i] = 1.0f / fmaxf((float)v, 1.0f);
        g_c[i] = (v > 0) ? 2.0f : 1.0f;
        g_fill[i] = 0;
    }
    if (blockIdx.x == NBLK - 1 && t == 0) g_rowptr[NN] = s_base + s_tot;
}
__global__ void k_fill(const int* __restrict__ ei) {
    int e = blockIdx.x * blockDim.x + threadIdx.x;
    if (e < NE) {
        int dst = ei[NE + e];
        int p = g_rowptr[dst] + atomicAdd(&g_fill[dst], 1);
        g_csr[p] = make_int2(ei[e], e);
    }
}

// merged weight prep: wsplit (blocks 0..511), r0 (512), bw (513), comb (514..641)
__global__ void k_prep(const float* __restrict__ Ws, const float* __restrict__ Wes,
                       const float* __restrict__ bs, const float* __restrict__ Wp,
                       const float* __restrict__ emb) {
    int b = blockIdx.x;
    if (b < 512) {
        int i = b * 256 + threadIdx.x;
        int l = i >> 15, rem = i & 32767;
        int k = rem >> 7, n = rem & 127;
        float v = (k < 128) ? Ws[l * 16384 + k * 128 + n]
                            : Wes[l * 16384 + (k - 128) * 128 + n];
        __nv_bfloat16 h = __float2bfloat16(v);
        g_Whi[i] = h;
        g_Wlo[i] = __float2bfloat16(v - __bfloat162float(h));
    } else if (b == 512) {
        int t = threadIdx.x;
        if (t < 128) {
            float acc = bs[t];
#pragma unroll 8
            for (int k = 0; k < 128; k++) acc = fmaf(emb[k], Ws[k * 128 + t], acc);
            g_t0[t] = acc;
        }
    } else if (b == 513) {
        int t = threadIdx.x;
        if (t < 128) {
            float acc = 0.f;
#pragma unroll 8
            for (int k = 0; k < 128; k++) acc = fmaf(bs[4 * 128 + k], Wp[k * 128 + t], acc);
            g_bw[t] = acc;
        }
    } else {
        int i = (b - 514) * 256 + threadIdx.x;
        int r = i >> 7, c = i & 127;
        const float* Wrow = (r < 128) ? (Ws + 4 * 16384 + r * 128)
                                      : (Wes + 4 * 16384 + (r - 128) * 128);
        float acc = 0.f;
#pragma unroll 8
        for (int k = 0; k < 128; k++) acc = fmaf(Wrow[k], Wp[k * 128 + c], acc);
        g_Wcomb[i] = acc;
    }
}

// V[i] = (sum edge_attr)/deg -> split bf16 (rows [row_base, row_base+nrows))
__global__ void k_v(const float* __restrict__ ea, int row_base, int nrows) {
    int gt = blockIdx.x * blockDim.x + threadIdx.x;
    int w = row_base + (gt >> 5), lane = gt & 31;
    if (w >= row_base + nrows) return;
    int s = g_rowptr[w], t = g_rowptr[w + 1];
    float4 acc = make_float4(0.f, 0.f, 0.f, 0.f);
    const float4* ea4 = (const float4*)ea;
    int p = s;
    for (; p + 1 < t; p += 2) {
        int2 c0 = g_csr[p], c1 = g_csr[p + 1];
        float4 x0 = ea4[c0.y * 32 + lane];
        float4 x1 = ea4[c1.y * 32 + lane];
        acc.x += x0.x + x1.x; acc.y += x0.y + x1.y;
        acc.z += x0.z + x1.z; acc.w += x0.w + x1.w;
    }
    if (p < t) {
        float4 x0 = ea4[g_csr[p].y * 32 + lane];
        acc.x += x0.x; acc.y += x0.y; acc.z += x0.z; acc.w += x0.w;
    }
    float id = g_invdeg[w];
    acc.x *= id; acc.y *= id; acc.z *= id; acc.w *= id;
    uint2 hi, lo; split4(acc, hi, lo);
    ((uint2*)g_vhi)[w * 32 + lane] = hi;
    ((uint2*)g_vlo)[w * 32 + lane] = lo;
}

// u = h + (sum h[src])/deg -> split bf16 (rows [row_base, row_base+nrows))
__global__ void k_spmm_split(const float* __restrict__ hin, int row_base, int nrows) {
    int gt = blockIdx.x * blockDim.x + threadIdx.x;
    int w = row_base + (gt >> 5), lane = gt & 31;
    if (w >= row_base + nrows) return;
    int s = g_rowptr[w], t = g_rowptr[w + 1];
    float4 acc = make_float4(0.f, 0.f, 0.f, 0.f);
    const float4* h4 = (const float4*)hin;
    int p = s;
    for (; p + 1 < t; p += 2) {
        int2 c0 = g_csr[p], c1 = g_csr[p + 1];
        float4 x0 = h4[c0.x * 32 + lane];
        float4 x1 = h4[c1.x * 32 + lane];
        acc.x += x0.x + x1.x; acc.y += x0.y + x1.y;
        acc.z += x0.z + x1.z; acc.w += x0.w + x1.w;
    }
    if (p < t) {
        float4 x0 = h4[g_csr[p].x * 32 + lane];
        acc.x += x0.x; acc.y += x0.y; acc.z += x0.z; acc.w += x0.w;
    }
    float id = g_invdeg[w];
    float4 hh = h4[w * 32 + lane];
    acc.x = hh.x + acc.x * id; acc.y = hh.y + acc.y * id;
    acc.z = hh.z + acc.z * id; acc.w = hh.w + acc.w * id;
    uint2 hi, lo; split4(acc, hi, lo);
    ((uint2*)g_uhi)[w * 32 + lane] = hi;
    ((uint2*)g_ulo)[w * 32 + lane] = lo;
}

// u (layer 4) -> fp32 for pooled path
__global__ void k_spmm_f32(const float* __restrict__ hin, int row_base, int nrows) {
    int gt = blockIdx.x * blockDim.x + threadIdx.x;
    int w = row_base + (gt >> 5), lane = gt & 31;
    if (w >= row_base + nrows) return;
    int s = g_rowptr[w], t = g_rowptr[w + 1];
    float4 acc = make_float4(0.f, 0.f, 0.f, 0.f);
    const float4* h4 = (const float4*)hin;
    int p = s;
    for (; p + 1 < t; p += 2) {
        int2 c0 = g_csr[p], c1 = g_csr[p + 1];
        float4 x0 = h4[c0.x * 32 + lane];
        float4 x1 = h4[c1.x * 32 + lane];
        acc.x += x0.x + x1.x; acc.y += x0.y + x1.y;
        acc.z += x0.z + x1.z; acc.w += x0.w + x1.w;
    }
    if (p < t) {
        float4 x0 = h4[g_csr[p].x * 32 + lane];
        acc.x += x0.x; acc.y += x0.y; acc.z += x0.z; acc.w += x0.w;
    }
    float id = g_invdeg[w];
    float4 hh = h4[w * 32 + lane];
    acc.x = hh.x + acc.x * id; acc.y = hh.y + acc.y * id;
    acc.z = hh.z + acc.z * id; acc.w = hh.w + acc.w * id;
    ((float4*)g_u32)[w * 32 + lane] = acc;
}

// hout = relu( [u|v] @ [W;We] + c*t )  — bf16x3 mma, cp.async double-buffered.
__global__ __launch_bounds__(256) void k_gemm(int layer, int first_stage,
                                              const float* __restrict__ tvec,
                                              float* __restrict__ hout,
                                              int row_base) {
    extern __shared__ char sm_[];
    __nv_bfloat16* As_hi = (__nv_bfloat16*)(sm_ + A_HI_OFF);
    __nv_bfloat16* As_lo = (__nv_bfloat16*)(sm_ + A_LO_OFF);
    __nv_bfloat16* Bs_hi = (__nv_bfloat16*)(sm_ + B_HI_OFF);
    __nv_bfloat16* Bs_lo = (__nv_bfloat16*)(sm_ + B_LO_OFF);
    float* sb = (float*)(sm_ + SB_OFF);

    int tid = threadIdx.x;
    int warp = tid >> 5, l = tid & 31;
    if (tid < 128) sb[tid] = tvec ? tvec[tid] : g_t0[tid];
    int row0 = row_base + blockIdx.x * 128;
    int wm = (warp >> 1) * 32, wn = (warp & 1) * 64;

    const __nv_bfloat16* Whi = g_Whi + layer * 32768;
    const __nv_bfloat16* Wlo = g_Wlo + layer * 32768;

    int ar = tid >> 1, asc = (tid & 1) * 2;
    int bk = tid >> 3, bsc = (tid & 7) * 2;

    auto issue = [&](int s, int buf) {
        const __nv_bfloat16* Ahi = (s < 4) ? g_uhi : g_vhi;
        const __nv_bfloat16* Alo = (s < 4) ? g_ulo : g_vlo;
        int akb = (s & 3) * 32;
        int grow = row0 + ar; if (grow >= NN) grow = NN - 1;
        const __nv_bfloat16* ah = Ahi + grow * 128 + akb + asc * 8;
        const __nv_bfloat16* al = Alo + grow * 128 + akb + asc * 8;
        uint32_t dh = sptr(As_hi + (buf * 128 + ar) * 40 + asc * 8);
        uint32_t dl = sptr(As_lo + (buf * 128 + ar) * 40 + asc * 8);
        CP16(dh, ah); CP16(dh + 16, ah + 8);
        CP16(dl, al); CP16(dl + 16, al + 8);
        const __nv_bfloat16* bh = Whi + (s * 32 + bk) * 128 + bsc * 8;
        const __nv_bfloat16* bl = Wlo + (s * 32 + bk) * 128 + bsc * 8;
        uint32_t eh = sptr(Bs_hi + (buf * 32 + bk) * 136 + bsc * 8);
        uint32_t el = sptr(Bs_lo + (buf * 32 + bk) * 136 + bsc * 8);
        CP16(eh, bh); CP16(eh + 16, bh + 8);
        CP16(el, bl); CP16(el + 16, bl + 8);
        CPCOMMIT();
    };

    float acc[2][8][4];
#pragma unroll
    for (int a = 0; a < 2; a++)
#pragma unroll
        for (int b = 0; b < 8; b++)
#pragma unroll
            for (int c = 0; c < 4; c++) acc[a][b][c] = 0.f;

    int rA = (l & 7) + ((l >> 3) & 1) * 8;
    int cA = (l >> 4) * 8;
    uint32_t aHi0 = sptr(As_hi + (wm + rA) * 40 + cA);
    uint32_t aLo0 = sptr(As_lo + (wm + rA) * 40 + cA);
    uint32_t bHi0 = sptr(Bs_hi + rA * 136 + wn + cA);
    uint32_t bLo0 = sptr(Bs_lo + rA * 136 + wn + cA);

    issue(first_stage, 0);
#pragma unroll 1
    for (int s = first_stage; s < 8; s++) {
        int buf = (s - first_stage) & 1;
        if (s + 1 < 8) issue(s + 1, buf ^ 1);
        if (s + 1 < 8) { CPWAIT(1); } else { CPWAIT(0); }
        __syncthreads();

        uint32_t aHi = aHi0 + buf * ABUF, aLo = aLo0 + buf * ABUF;
        uint32_t bHi = bHi0 + buf * BBUF, bLo = bLo0 + buf * BBUF;
#pragma unroll
        for (int ks = 0; ks < 2; ks++) {
            int k16 = ks * 16;
            uint32_t ah[2][4], al[2][4];
#pragma unroll
            for (int mt = 0; mt < 2; mt++) {
                LDSM4(ah[mt], aHi + (mt * 16 * 40 + k16) * 2);
                LDSM4(al[mt], aLo + (mt * 16 * 40 + k16) * 2);
            }
#pragma unroll
            for (int ng = 0; ng < 4; ng++) {
                uint32_t bh[4], bl[4];
                LDSM4T(bh, bHi + (k16 * 136 + ng * 16) * 2);
                LDSM4T(bl, bLo + (k16 * 136 + ng * 16) * 2);
#pragma unroll
                for (int mt = 0; mt < 2; mt++) {
#pragma unroll
                    for (int sub = 0; sub < 2; sub++) {
                        float* C = acc[mt][ng * 2 + sub];
                        MMA(C, ah[mt], &bh[sub * 2]);
                        MMA(C, ah[mt], &bl[sub * 2]);
                        MMA(C, al[mt], &bh[sub * 2]);
                    }
                }
            }
        }
        __syncthreads();
    }

    int gq = l >> 2, tg = l & 3;
#pragma unroll
    for (int mt = 0; mt < 2; mt++) {
        int r1 = row0 + wm + mt * 16 + gq;
        int r2 = r1 + 8;
        float c1 = (r1 < NN) ? g_c[r1] : 0.f;
        float c2 = (r2 < NN) ? g_c[r2] : 0.f;
#pragma unroll
        for (int nt = 0; nt < 8; nt++) {
            int col = wn + nt * 8 + tg * 2;
            float b0 = sb[col], b1 = sb[col + 1];
            float* C = acc[mt][nt];
            float v0 = fmaxf(C[0] + c1 * b0, 0.f), v1 = fmaxf(C[1] + c1 * b1, 0.f);
            float v2 = fmaxf(C[2] + c2 * b0, 0.f), v3 = fmaxf(C[3] + c2 * b1, 0.f);
            if (r1 < NN) *(float2*)&hout[r1 * 128 + col] = make_float2(v0, v1);
            if (r2 < NN) *(float2*)&hout[r2 * 128 + col] = make_float2(v2, v3);
        }
    }
}

// ---------------- fused pool + collapsed last layer + classifier ------------
__device__ __forceinline__ int lower_bound(const int* a, int n, int key) {
    int lo = 0, hi = n;
    while (lo < hi) {
        int mid = (lo + hi) >> 1;
        if (a[mid] < key) lo = mid + 1; else hi = mid;
    }
    return lo;
}

__global__ void k_pool_out(const int* __restrict__ batch,
                           const float* __restrict__ bp,
                           float* __restrict__ out) {
    int g = blockIdx.x, t = threadIdx.x;
    __shared__ int s_lo, s_hi;
    __shared__ float sp[256];
    __shared__ float spc[256];
    if (t == 0) s_lo = lower_bound(batch, NN, g);
    if (t == 1) s_hi = lower_bound(batch, NN, g + 1);
    __syncthreads();
    int lo = s_lo, hi = s_hi;
    float sum = 0.f;
    if (t < 128) {
        for (int r = lo; r < hi; r++) sum += g_u32[r * 128 + t];
    } else {
        int q = t - 128;
        for (int r = lo; r < hi; r++)
            sum += __bfloat162float(g_vhi[r * 128 + q]) + __bfloat162float(g_vlo[r * 128 + q]);
    }
    float csum = 0.f;
    for (int r = lo + t; r < hi; r += 256) csum += g_c[r];
    float inv = 1.f / fmaxf((float)(hi - lo), 1.f);
    sp[t] = sum * inv;
    spc[t] = csum;
    __syncthreads();
#pragma unroll
    for (int s = 128; s > 0; s >>= 1) {
        if (t < s) spc[t] += spc[t + s];
        __syncthreads();
    }
    float pcm = spc[0] * inv;
    if (t < 128) {
        float acc = fmaf(pcm, g_bw[t], bp[t]);
#pragma unroll 8
        for (int k = 0; k < 256; k++) acc = fmaf(sp[k], g_Wcomb[k * 128 + t], acc);
        out[g * 128 + t] = acc;
    }
}

// ---------------- launch ----------------------------------------------------
extern "C" void kernel_launch(void* const* d_in, const int* in_sizes, int n_in,
                              void* d_out, int out_size) {
    const int*   ei    = (const int*)d_in[1];
    const float* ea    = (const float*)d_in[2];
    const int*   batch = (const int*)d_in[3];
    const float* emb   = (const float*)d_in[4];
    const float* Ws    = (const float*)d_in[5];
    const float* bs    = (const float*)d_in[6];
    const float* Wes   = (const float*)d_in[7];
    const float* Wp    = (const float*)d_in[8];
    const float* bp    = (const float*)d_in[9];
    float* out = (float*)d_out;

    static cudaStream_t s1 = 0, s2 = 0;
    static cudaEvent_t ev[16];
    static int initialized = 0;
    if (!initialized) {
        initialized = 1;
        cudaFuncSetAttribute(k_gemm, cudaFuncAttributeMaxDynamicSharedMemorySize,
                             GEMM_SMEM);
        bool ok = (cudaStreamCreateWithFlags(&s1, cudaStreamNonBlocking) == cudaSuccess) &&
                  (cudaStreamCreateWithFlags(&s2, cudaStreamNonBlocking) == cudaSuccess);
        for (int i = 0; i < 16 && ok; i++)
            ok = (cudaEventCreateWithFlags(&ev[i], cudaEventDisableTiming) == cudaSuccess);
        if (!ok) { s1 = 0; s2 = 0; }
    }
    bool par = (s1 != 0) && (s2 != 0);
    cudaStream_t A = par ? s1 : 0;
    cudaStream_t B = par ? s2 : 0;

    float *ha, *hb;
    cudaGetSymbolAddress((void**)&ha, g_ha);
    cudaGetSymbolAddress((void**)&hb, g_hb);

    if (par) {
        cudaEventRecord(ev[0], 0);
        cudaStreamWaitEvent(s1, ev[0], 0);
        cudaStreamWaitEvent(s2, ev[0], 0);
    }

    // CSR chain on A; weight prep on B
    k_zero<<<NBLK, 256, 0, A>>>();
    k_count<<<(NE + 255) / 256, 256, 0, A>>>(ei);
    k_scan1<<<NBLK, 256, 0, A>>>();
    k_scan3z<<<NBLK, 256, 0, A>>>();
    k_fill<<<(NE + 255) / 256, 256, 0, A>>>(ei);
    k_prep<<<642, 256, 0, B>>>(Ws, Wes, bs, Wp, emb);
    if (par) cudaEventRecord(ev[1], B);                 // prep done

    // k_v halves (staggered so gemm0A overlaps k_vB)
    k_v<<<GR_A_SPMM, 256, 0, A>>>(ea, 0, ROWS_A);
    if (par) cudaEventRecord(ev[2], A);                 // kvA (implies fill)
    if (par) cudaStreamWaitEvent(B, ev[2], 0);
    k_v<<<GR_B_SPMM, 256, 0, B>>>(ea, ROWS_A, ROWS_B);

    // layer 0: gemm halves (rank-1 shortcut, K=128: stages 4..7 read v)
    if (par) cudaStreamWaitEvent(A, ev[1], 0);          // needs weights+t0
    k_gemm<<<TILE_A, 256, GEMM_SMEM, A>>>(0, 4, nullptr, ha, 0);
    k_gemm<<<TILE_B, 256, GEMM_SMEM, B>>>(0, 4, nullptr, ha, ROWS_A);
    if (par) cudaEventRecord(ev[3], B);                 // g0B done

    // layers 1..3: staggered two-stream pipeline, ping-pong h buffers
    const float* hcur = ha;
    float* hnxt = hb;
    int eb = 4;
    for (int l = 1; l <= 3; l++) {
        cudaEvent_t eSA = ev[eb], eGB = ev[eb + 1]; eb += 2;
        if (par) cudaStreamWaitEvent(A, (l == 1) ? ev[3] : ev[eb - 3], 0); // prev gemmB
        k_spmm_split<<<GR_A_SPMM, 256, 0, A>>>(hcur, 0, ROWS_A);
        if (par) cudaEventRecord(eSA, A);
        k_gemm<<<TILE_A, 256, GEMM_SMEM, A>>>(l, 0, bs + l * 128, hnxt, 0);
        if (par) cudaStreamWaitEvent(B, eSA, 0);
        k_spmm_split<<<GR_B_SPMM, 256, 0, B>>>(hcur, ROWS_A, ROWS_B);
        k_gemm<<<TILE_B, 256, GEMM_SMEM, B>>>(l, 0, bs + l * 128, hnxt, ROWS_A);
        if (par) cudaEventRecord(eGB, B);
        const float* tmp = hcur; hcur = hnxt; hnxt = (float*)tmp;
    }
    // after loop: eb == 10; last gemmB event is ev[9]

    // layer 4 collapsed: spmm_f32 halves, then pooled classifier
    if (par) cudaStreamWaitEvent(A, ev[9], 0);
    k_spmm_f32<<<GR_A_SPMM, 256, 0, A>>>(hcur, 0, ROWS_A);
    if (par) cudaEventRecord(ev[10], A);
    if (par) cudaStreamWaitEvent(B, ev[10], 0);
    k_spmm_f32<<<GR_B_SPMM, 256, 0, B>>>(hcur, ROWS_A, ROWS_B);
    if (par) cudaEventRecord(ev[11], B);
    if (par) cudaStreamWaitEvent(A, ev[11], 0);
    k_pool_out<<<NG, 256, 0, A>>>(batch, bp, out);

    if (par) {
        cudaEventRecord(ev[12], A);
        cudaStreamWaitEvent(0, ev[12], 0);   // join back to capture origin
    }
}

// round 7
// speedup vs baseline: 1.2615x; 1.0978x over previous
#include <cuda_runtime.h>
#include <cuda_bf16.h>
#include <cstdint>

#define NN 50000
#define NE 640000
#define D  128
#define NG 512
#define NBLK ((NN + 255) / 256)
#define NTILE ((NN + 127) / 128)
#define GR_SPMM ((NN * 32 + 255) / 256)

// dynamic smem layout for k_gemm (bytes)
#define A_HI_OFF 0        // [2][128][40] bf16 : 2*10240
#define A_LO_OFF 20480
#define B_HI_OFF 40960    // [2][32][136] bf16 : 2*8704
#define B_LO_OFF 58368
#define SB_OFF   75776    // float[128]
#define GEMM_SMEM 76288
#define ABUF 10240
#define BBUF 8704

// ---------------- scratch (static device globals) --------------------------
__device__ __align__(16) float g_h[NN * D];
__device__ __align__(16) float g_u32[NN * D];
__device__ __align__(16) __nv_bfloat16 g_uhi[NN * D];
__device__ __align__(16) __nv_bfloat16 g_ulo[NN * D];
__device__ __align__(16) __nv_bfloat16 g_vhi[NN * D];
__device__ __align__(16) __nv_bfloat16 g_vlo[NN * D];
__device__ __align__(16) __nv_bfloat16 g_Whi[4 * 256 * 128];
__device__ __align__(16) __nv_bfloat16 g_Wlo[4 * 256 * 128];
__device__ __align__(16) float g_Wcomb[256 * 128];
__device__ float g_bw[128];
__device__ float g_t0[128];
__device__ float g_invdeg[NN];
__device__ float g_c[NN];
__device__ int   g_indeg[NN];
__device__ int   g_rowptr[NN + 1];
__device__ int   g_fill[NN];
__device__ int   g_bsum[NBLK + 32];
__device__ __align__(8) int2 g_csr[NE];     // (src, eid)

// ---------------- helpers ---------------------------------------------------
__device__ __forceinline__ unsigned short bf_bits(__nv_bfloat16 h) {
    unsigned short u; memcpy(&u, &h, 2); return u;
}
__device__ __forceinline__ void split4(float4 a, uint2& hi, uint2& lo) {
    __nv_bfloat16 h0 = __float2bfloat16(a.x), h1 = __float2bfloat16(a.y);
    __nv_bfloat16 h2 = __float2bfloat16(a.z), h3 = __float2bfloat16(a.w);
    __nv_bfloat16 l0 = __float2bfloat16(a.x - __bfloat162float(h0));
    __nv_bfloat16 l1 = __float2bfloat16(a.y - __bfloat162float(h1));
    __nv_bfloat16 l2 = __float2bfloat16(a.z - __bfloat162float(h2));
    __nv_bfloat16 l3 = __float2bfloat16(a.w - __bfloat162float(h3));
    hi.x = (unsigned)bf_bits(h0) | ((unsigned)bf_bits(h1) << 16);
    hi.y = (unsigned)bf_bits(h2) | ((unsigned)bf_bits(h3) << 16);
    lo.x = (unsigned)bf_bits(l0) | ((unsigned)bf_bits(l1) << 16);
    lo.y = (unsigned)bf_bits(l2) | ((unsigned)bf_bits(l3) << 16);
}
__device__ __forceinline__ uint32_t sptr(const void* p) {
    return (uint32_t)__cvta_generic_to_shared(p);
}

#define LDSM4(R, addr) \
    asm volatile("ldmatrix.sync.aligned.m8n8.x4.shared.b16 {%0,%1,%2,%3},[%4];" \
        : "=r"((R)[0]), "=r"((R)[1]), "=r"((R)[2]), "=r"((R)[3]) : "r"(addr))
#define LDSM4T(R, addr) \
    asm volatile("ldmatrix.sync.aligned.m8n8.x4.trans.shared.b16 {%0,%1,%2,%3},[%4];" \
        : "=r"((R)[0]), "=r"((R)[1]), "=r"((R)[2]), "=r"((R)[3]) : "r"(addr))
#define MMA(C, A, B) \
    asm volatile("mma.sync.aligned.m16n8k16.row.col.f32.bf16.bf16.f32 " \
        "{%0,%1,%2,%3},{%4,%5,%6,%7},{%8,%9},{%0,%1,%2,%3};" \
        : "+f"((C)[0]), "+f"((C)[1]), "+f"((C)[2]), "+f"((C)[3]) \
        : "r"((A)[0]), "r"((A)[1]), "r"((A)[2]), "r"((A)[3]), "r"((B)[0]), "r"((B)[1]))
#define CP16(dst, src) \
    asm volatile("cp.async.cg.shared.global [%0], [%1], 16;" :: "r"(dst), "l"(src))
#define CPCOMMIT() asm volatile("cp.async.commit_group;")
#define CPWAIT(n)  asm volatile("cp.async.wait_group %0;" :: "n"(n))

// ---------------- init / CSR build -----------------------------------------
__global__ void k_zero() {
    int i = blockIdx.x * blockDim.x + threadIdx.x;
    if (i < NN) g_indeg[i] = 0;
}
__global__ void k_count(const int* __restrict__ ei) {
    int e = blockIdx.x * blockDim.x + threadIdx.x;
    if (e < NE) atomicAdd(&g_indeg[ei[NE + e]], 1);
}
__global__ void k_scan1() {
    __shared__ int sm[8];
    int t = threadIdx.x, lane = t & 31, wid = t >> 5;
    int i = blockIdx.x * 256 + t;
    int v = (i < NN) ? g_indeg[i] : 0;
#pragma unroll
    for (int s = 16; s > 0; s >>= 1) v += __shfl_down_sync(0xffffffffu, v, s);
    if (lane == 0) sm[wid] = v;
    __syncthreads();
    if (t == 0) {
        int s = 0;
#pragma unroll
        for (int w = 0; w < 8; w++) s += sm[w];
        g_bsum[blockIdx.x] = s;
    }
}
// block-local scan + in-kernel offset reduction; also invdeg/c and fill=0
__global__ void k_scan3z() {
    __shared__ int red[8];
    __shared__ int ws[8];
    __shared__ int s_base, s_tot;
    int t = threadIdx.x, lane = t & 31, wid = t >> 5;
    int part = 0;
    for (int j = t; j < blockIdx.x; j += 256) part += g_bsum[j];
#pragma unroll
    for (int s = 16; s > 0; s >>= 1) part += __shfl_down_sync(0xffffffffu, part, s);
    if (lane == 0) red[wid] = part;
    __syncthreads();
    if (t == 0) {
        int b = 0;
#pragma unroll
        for (int w = 0; w < 8; w++) b += red[w];
        s_base = b;
    }
    int i = blockIdx.x * 256 + t;
    int v = (i < NN) ? g_indeg[i] : 0;
    int x = v;
#pragma unroll
    for (int s = 1; s < 32; s <<= 1) {
        int tt = __shfl_up_sync(0xffffffffu, x, s);
        if (lane >= s) x += tt;
    }
    if (lane == 31) ws[wid] = x;
    __syncthreads();
    if (t == 0) {
        int acc = 0;
#pragma unroll
        for (int w = 0; w < 8; w++) { int tmp = ws[w]; ws[w] = acc; acc += tmp; }
        s_tot = acc;
    }
    __syncthreads();
    if (i < NN) {
        g_rowptr[i] = s_base + ws[wid] + x - v;
        g_invdeg[i] = 1.0f / fmaxf((float)v, 1.0f);
        g_c[i] = (v > 0) ? 2.0f : 1.0f;
        g_fill[i] = 0;
    }
    if (blockIdx.x == NBLK - 1 && t == 0) g_rowptr[NN] = s_base + s_tot;
}
__global__ void k_fill(const int* __restrict__ ei) {
    int e = blockIdx.x * blockDim.x + threadIdx.x;
    if (e < NE) {
        int dst = ei[NE + e];
        int p = g_rowptr[dst] + atomicAdd(&g_fill[dst], 1);
        g_csr[p] = make_int2(ei[e], e);
    }
}

// merged weight prep: wsplit (blocks 0..511), r0 (512), bw (513), comb (514..641)
__global__ void k_prep(const float* __restrict__ Ws, const float* __restrict__ Wes,
                       const float* __restrict__ bs, const float* __restrict__ Wp,
                       const float* __restrict__ emb) {
    int b = blockIdx.x;
    if (b < 512) {
        int i = b * 256 + threadIdx.x;
        int l = i >> 15, rem = i & 32767;
        int k = rem >> 7, n = rem & 127;
        float v = (k < 128) ? Ws[l * 16384 + k * 128 + n]
                            : Wes[l * 16384 + (k - 128) * 128 + n];
        __nv_bfloat16 h = __float2bfloat16(v);
        g_Whi[i] = h;
        g_Wlo[i] = __float2bfloat16(v - __bfloat162float(h));
    } else if (b == 512) {
        int t = threadIdx.x;
        if (t < 128) {
            float acc = bs[t];
#pragma unroll 8
            for (int k = 0; k < 128; k++) acc = fmaf(emb[k], Ws[k * 128 + t], acc);
            g_t0[t] = acc;
        }
    } else if (b == 513) {
        int t = threadIdx.x;
        if (t < 128) {
            float acc = 0.f;
#pragma unroll 8
            for (int k = 0; k < 128; k++) acc = fmaf(bs[4 * 128 + k], Wp[k * 128 + t], acc);
            g_bw[t] = acc;
        }
    } else {
        int i = (b - 514) * 256 + threadIdx.x;
        int r = i >> 7, c = i & 127;
        const float* Wrow = (r < 128) ? (Ws + 4 * 16384 + r * 128)
                                      : (Wes + 4 * 16384 + (r - 128) * 128);
        float acc = 0.f;
#pragma unroll 8
        for (int k = 0; k < 128; k++) acc = fmaf(Wrow[k], Wp[k * 128 + c], acc);
        g_Wcomb[i] = acc;
    }
}

// V[i] = (sum edge_attr)/deg -> split bf16
__global__ void k_v(const float* __restrict__ ea) {
    int gt = blockIdx.x * blockDim.x + threadIdx.x;
    int w = gt >> 5, lane = gt & 31;
    if (w >= NN) return;
    int s = g_rowptr[w], t = g_rowptr[w + 1];
    float4 acc = make_float4(0.f, 0.f, 0.f, 0.f);
    const float4* ea4 = (const float4*)ea;
    int p = s;
    for (; p + 1 < t; p += 2) {
        int2 c0 = g_csr[p], c1 = g_csr[p + 1];
        float4 x0 = ea4[c0.y * 32 + lane];
        float4 x1 = ea4[c1.y * 32 + lane];
        acc.x += x0.x + x1.x; acc.y += x0.y + x1.y;
        acc.z += x0.z + x1.z; acc.w += x0.w + x1.w;
    }
    if (p < t) {
        float4 x0 = ea4[g_csr[p].y * 32 + lane];
        acc.x += x0.x; acc.y += x0.y; acc.z += x0.z; acc.w += x0.w;
    }
    float id = g_invdeg[w];
    acc.x *= id; acc.y *= id; acc.z *= id; acc.w *= id;
    uint2 hi, lo; split4(acc, hi, lo);
    ((uint2*)g_vhi)[w * 32 + lane] = hi;
    ((uint2*)g_vlo)[w * 32 + lane] = lo;
}

// u = h + (sum h[src])/deg -> split bf16
__global__ void k_spmm_split() {
    int gt = blockIdx.x * blockDim.x + threadIdx.x;
    int w = gt >> 5, lane = gt & 31;
    if (w >= NN) return;
    int s = g_rowptr[w], t = g_rowptr[w + 1];
    float4 acc = make_float4(0.f, 0.f, 0.f, 0.f);
    const float4* h4 = (const float4*)g_h;
    int p = s;
    for (; p + 1 < t; p += 2) {
        int2 c0 = g_csr[p], c1 = g_csr[p + 1];
        float4 x0 = h4[c0.x * 32 + lane];
        float4 x1 = h4[c1.x * 32 + lane];
        acc.x += x0.x + x1.x; acc.y += x0.y + x1.y;
        acc.z += x0.z + x1.z; acc.w += x0.w + x1.w;
    }
    if (p < t) {
        float4 x0 = h4[g_csr[p].x * 32 + lane];
        acc.x += x0.x; acc.y += x0.y; acc.z += x0.z; acc.w += x0.w;
    }
    float id = g_invdeg[w];
    float4 hh = h4[w * 32 + lane];
    acc.x = hh.x + acc.x * id; acc.y = hh.y + acc.y * id;
    acc.z = hh.z + acc.z * id; acc.w = hh.w + acc.w * id;
    uint2 hi, lo; split4(acc, hi, lo);
    ((uint2*)g_uhi)[w * 32 + lane] = hi;
    ((uint2*)g_ulo)[w * 32 + lane] = lo;
}

// u (layer 4) -> fp32 for pooled path
__global__ void k_spmm_f32() {
    int gt = blockIdx.x * blockDim.x + threadIdx.x;
    int w = gt >> 5, lane = gt & 31;
    if (w >= NN) return;
    int s = g_rowptr[w], t = g_rowptr[w + 1];
    float4 acc = make_float4(0.f, 0.f, 0.f, 0.f);
    const float4* h4 = (const float4*)g_h;
    int p = s;
    for (; p + 1 < t; p += 2) {
        int2 c0 = g_csr[p], c1 = g_csr[p + 1];
        float4 x0 = h4[c0.x * 32 + lane];
        float4 x1 = h4[c1.x * 32 + lane];
        acc.x += x0.x + x1.x; acc.y += x0.y + x1.y;
        acc.z += x0.z + x1.z; acc.w += x0.w + x1.w;
    }
    if (p < t) {
        float4 x0 = h4[g_csr[p].x * 32 + lane];
        acc.x += x0.x; acc.y += x0.y; acc.z += x0.z; acc.w += x0.w;
    }
    float id = g_invdeg[w];
    float4 hh = h4[w * 32 + lane];
    acc.x = hh.x + acc.x * id; acc.y = hh.y + acc.y * id;
    acc.z = hh.z + acc.z * id; acc.w = hh.w + acc.w * id;
    ((float4*)g_u32)[w * 32 + lane] = acc;
}

// g_h = relu( [u|v] @ [W;We] + c*t )  — bf16x3 mma, cp.async double-buffered.
__global__ __launch_bounds__(256, 2) void k_gemm(int layer, int first_stage,
                                                 const float* __restrict__ tvec) {
    extern __shared__ char sm_[];
    __nv_bfloat16* As_hi = (__nv_bfloat16*)(sm_ + A_HI_OFF);
    __nv_bfloat16* As_lo = (__nv_bfloat16*)(sm_ + A_LO_OFF);
    __nv_bfloat16* Bs_hi = (__nv_bfloat16*)(sm_ + B_HI_OFF);
    __nv_bfloat16* Bs_lo = (__nv_bfloat16*)(sm_ + B_LO_OFF);
    float* sb = (float*)(sm_ + SB_OFF);

    int tid = threadIdx.x;
    int warp = tid >> 5, l = tid & 31;
    if (tid < 128) sb[tid] = tvec ? tvec[tid] : g_t0[tid];
    int row0 = blockIdx.x * 128;
    int wm = (warp >> 1) * 32, wn = (warp & 1) * 64;

    const __nv_bfloat16* Whi = g_Whi + layer * 32768;
    const __nv_bfloat16* Wlo = g_Wlo + layer * 32768;

    int ar = tid >> 1, asc = (tid & 1) * 2;
    int bk = tid >> 3, bsc = (tid & 7) * 2;

    auto issue = [&](int s, int buf) {
        const __nv_bfloat16* Ahi = (s < 4) ? g_uhi : g_vhi;
        const __nv_bfloat16* Alo = (s < 4) ? g_ulo : g_vlo;
        int akb = (s & 3) * 32;
        int grow = row0 + ar; if (grow >= NN) grow = NN - 1;
        const __nv_bfloat16* ah = Ahi + grow * 128 + akb + asc * 8;
        const __nv_bfloat16* al = Alo + grow * 128 + akb + asc * 8;
        uint32_t dh = sptr(As_hi + (buf * 128 + ar) * 40 + asc * 8);
        uint32_t dl = sptr(As_lo + (buf * 128 + ar) * 40 + asc * 8);
        CP16(dh, ah); CP16(dh + 16, ah + 8);
        CP16(dl, al); CP16(dl + 16, al + 8);
        const __nv_bfloat16* bh = Whi + (s * 32 + bk) * 128 + bsc * 8;
        const __nv_bfloat16* bl = Wlo + (s * 32 + bk) * 128 + bsc * 8;
        uint32_t eh = sptr(Bs_hi + (buf * 32 + bk) * 136 + bsc * 8);
        uint32_t el = sptr(Bs_lo + (buf * 32 + bk) * 136 + bsc * 8);
        CP16(eh, bh); CP16(eh + 16, bh + 8);
        CP16(el, bl); CP16(el + 16, bl + 8);
        CPCOMMIT();
    };

    float acc[2][8][4];
#pragma unroll
    for (int a = 0; a < 2; a++)
#pragma unroll
        for (int b = 0; b < 8; b++)
#pragma unroll
            for (int c = 0; c < 4; c++) acc[a][b][c] = 0.f;

    int rA = (l & 7) + ((l >> 3) & 1) * 8;
    int cA = (l >> 4) * 8;
    uint32_t aHi0 = sptr(As_hi + (wm + rA) * 40 + cA);
    uint32_t aLo0 = sptr(As_lo + (wm + rA) * 40 + cA);
    uint32_t bHi0 = sptr(Bs_hi + rA * 136 + wn + cA);
    uint32_t bLo0 = sptr(Bs_lo + rA * 136 + wn + cA);

    issue(first_stage, 0);
#pragma unroll 1
    for (int s = first_stage; s < 8; s++) {
        int buf = (s - first_stage) & 1;
        if (s + 1 < 8) issue(s + 1, buf ^ 1);
        if (s + 1 < 8) { CPWAIT(1); } else { CPWAIT(0); }
        __syncthreads();

        uint32_t aHi = aHi0 + buf * ABUF, aLo = aLo0 + buf * ABUF;
        uint32_t bHi = bHi0 + buf * BBUF, bLo = bLo0 + buf * BBUF;
#pragma unroll
        for (int ks = 0; ks < 2; ks++) {
            int k16 = ks * 16;
            uint32_t ah[2][4], al[2][4];
#pragma unroll
            for (int mt = 0; mt < 2; mt++) {
                LDSM4(ah[mt], aHi + (mt * 16 * 40 + k16) * 2);
                LDSM4(al[mt], aLo + (mt * 16 * 40 + k16) * 2);
            }
#pragma unroll
            for (int ng = 0; ng < 4; ng++) {
                uint32_t bh[4], bl[4];
                LDSM4T(bh, bHi + (k16 * 136 + ng * 16) * 2);
                LDSM4T(bl, bLo + (k16 * 136 + ng * 16) * 2);
#pragma unroll
                for (int mt = 0; mt < 2; mt++) {
#pragma unroll
                    for (int sub = 0; sub < 2; sub++) {
                        float* C = acc[mt][ng * 2 + sub];
                        MMA(C, ah[mt], &bh[sub * 2]);
                        MMA(C, ah[mt], &bl[sub * 2]);
                        MMA(C, al[mt], &bh[sub * 2]);
                    }
                }
            }
        }
        __syncthreads();
    }

    int gq = l >> 2, tg = l & 3;
#pragma unroll
    for (int mt = 0; mt < 2; mt++) {
        int r1 = row0 + wm + mt * 16 + gq;
        int r2 = r1 + 8;
        float c1 = (r1 < NN) ? g_c[r1] : 0.f;
        float c2 = (r2 < NN) ? g_c[r2] : 0.f;
#pragma unroll
        for (int nt = 0; nt < 8; nt++) {
            int col = wn + nt * 8 + tg * 2;
            float b0 = sb[col], b1 = sb[col + 1];
            float* C = acc[mt][nt];
            float v0 = fmaxf(C[0] + c1 * b0, 0.f), v1 = fmaxf(C[1] + c1 * b1, 0.f);
            float v2 = fmaxf(C[2] + c2 * b0, 0.f), v3 = fmaxf(C[3] + c2 * b1, 0.f);
            if (r1 < NN) *(float2*)&g_h[r1 * 128 + col] = make_float2(v0, v1);
            if (r2 < NN) *(float2*)&g_h[r2 * 128 + col] = make_float2(v2, v3);
        }
    }
}

// ---------------- fused pool + collapsed last layer + classifier ------------
__device__ __forceinline__ int lower_bound(const int* a, int n, int key) {
    int lo = 0, hi = n;
    while (lo < hi) {
        int mid = (lo + hi) >> 1;
        if (a[mid] < key) lo = mid + 1; else hi = mid;
    }
    return lo;
}

__global__ void k_pool_out(const int* __restrict__ batch,
                           const float* __restrict__ bp,
                           float* __restrict__ out) {
    int g = blockIdx.x, t = threadIdx.x;
    __shared__ int s_lo, s_hi;
    __shared__ float sp[256];
    __shared__ float spc[256];
    if (t == 0) s_lo = lower_bound(batch, NN, g);
    if (t == 1) s_hi = lower_bound(batch, NN, g + 1);
    __syncthreads();
    int lo = s_lo, hi = s_hi;
    float sum = 0.f;
    if (t < 128) {
        for (int r = lo; r < hi; r++) sum += g_u32[r * 128 + t];
    } else {
        int q = t - 128;
        for (int r = lo; r < hi; r++)
            sum += __bfloat162float(g_vhi[r * 128 + q]) + __bfloat162float(g_vlo[r * 128 + q]);
    }
    float csum = 0.f;
    for (int r = lo + t; r < hi; r += 256) csum += g_c[r];
    float inv = 1.f / fmaxf((float)(hi - lo), 1.f);
    sp[t] = sum * inv;
    spc[t] = csum;
    __syncthreads();
#pragma unroll
    for (int s = 128; s > 0; s >>= 1) {
        if (t < s) spc[t] += spc[t + s];
        __syncthreads();
    }
    float pcm = spc[0] * inv;
    if (t < 128) {
        float acc = fmaf(pcm, g_bw[t], bp[t]);
#pragma unroll 8
        for (int k = 0; k < 256; k++) acc = fmaf(sp[k], g_Wcomb[k * 128 + t], acc);
        out[g * 128 + t] = acc;
    }
}

// ---------------- launch ----------------------------------------------------
extern "C" void kernel_launch(void* const* d_in, const int* in_sizes, int n_in,
                              void* d_out, int out_size) {
    const int*   ei    = (const int*)d_in[1];
    const float* ea    = (const float*)d_in[2];
    const int*   batch = (const int*)d_in[3];
    const float* emb   = (const float*)d_in[4];
    const float* Ws    = (const float*)d_in[5];
    const float* bs    = (const float*)d_in[6];
    const float* Wes   = (const float*)d_in[7];
    const float* Wp    = (const float*)d_in[8];
    const float* bp    = (const float*)d_in[9];
    float* out = (float*)d_out;

    static cudaStream_t sB = 0;
    static cudaEvent_t evFork = 0, evPrep = 0;
    static int initialized = 0;
    if (!initialized) {
        initialized = 1;
        cudaFuncSetAttribute(k_gemm, cudaFuncAttributeMaxDynamicSharedMemorySize,
                             GEMM_SMEM);
        bool ok = (cudaStreamCreateWithFlags(&sB, cudaStreamNonBlocking) == cudaSuccess) &&
                  (cudaEventCreateWithFlags(&evFork, cudaEventDisableTiming) == cudaSuccess) &&
                  (cudaEventCreateWithFlags(&evPrep, cudaEventDisableTiming) == cudaSuccess);
        if (!ok) sB = 0;
    }
    bool par = (sB != 0);

    // weight prep on side stream (independent of CSR chain)
    if (par) {
        cudaEventRecord(evFork, 0);
        cudaStreamWaitEvent(sB, evFork, 0);
        k_prep<<<642, 256, 0, sB>>>(Ws, Wes, bs, Wp, emb);
        cudaEventRecord(evPrep, sB);
    } else {
        k_prep<<<642, 256>>>(Ws, Wes, bs, Wp, emb);
    }

    // CSR chain + layers on the main stream, full-grid each
    k_zero<<<NBLK, 256>>>();
    k_count<<<(NE + 255) / 256, 256>>>(ei);
    k_scan1<<<NBLK, 256>>>();
    k_scan3z<<<NBLK, 256>>>();
    k_fill<<<(NE + 255) / 256, 256>>>(ei);
    k_v<<<GR_SPMM, 256>>>(ea);

    if (par) cudaStreamWaitEvent(0, evPrep, 0);   // weights/t0 ready
    // layer 0: rank-1 shortcut, K=128 (v@We0 only)
    k_gemm<<<NTILE, 256, GEMM_SMEM>>>(0, 4, nullptr);
    // layers 1..3
    for (int l = 1; l < 4; l++) {
        k_spmm_split<<<GR_SPMM, 256>>>();
        k_gemm<<<NTILE, 256, GEMM_SMEM>>>(l, 0, bs + l * 128);
    }
    // layer 4 collapsed into pooled path
    k_spmm_f32<<<GR_SPMM, 256>>>();
    k_pool_out<<<NG, 256>>>(batch, bp, out);
}